// round 4
// baseline (speedup 1.0000x reference)
#include <cuda_runtime.h>

// Persistent-kernel TV denoiser (Chambolle-Pock, RHO-relaxed), single launch.
// 512 blocks x 256 threads; each thread owns 2 adjacent columns (float2) and
// marches an 8-row stripe. Neighbor-only sync between iterations; global
// convergence decision evaluated with 1-iteration slack (ping-pong-safe).

#define BATCH 8
#define HH 512
#define WW 512
#define IMG (HH*WW)
#define NTOT (BATCH*IMG)
#define ROWS 8
#define SPI (HH/ROWS)            // 64 stripes per image
#define NBLK (BATCH*SPI)         // 512 blocks, one stripe each
#define NTHR 256
#define NWARP (NTHR/32)

#define TAUc     0.01f
#define INV1PTAU (1.0f/1.01f)
#define SIGMAc   12.5f
#define RHOc     1.99f
#define HRHOc    0.995f          /* RHO/2 */
#define THSc     0.1f
#define THS2c    0.01f           /* THS^2 */
#define CRITc    1e-5f
#define NITERc   40

__device__ float g_x [2][NTOT];
__device__ float g_u0[2][NTOT];
__device__ float g_u1[2][NTOT];
__device__ float g_pnum[NITERc][NBLK];
__device__ float g_pden[NITERc][NBLK];
__device__ volatile int g_ptag[NITERc][NBLK];   // monotonic across graph replays
__device__ volatile int g_vflag[NBLK];          // monotonic version counters

// Compute z = 2x - x2 for this thread's column pair at row i, plus the lane-31
// fixup column (c0+2). u0prev / u0fixprev are the previous-row u0 values
// (register-carried). Contains warp shuffles: call only with block-uniform i.
__device__ __forceinline__ void row_pair(
    const float* __restrict__ xin, const float* __restrict__ u0in,
    const float* __restrict__ u1in, const float* __restrict__ yv,
    int g, int i, int tid, int lane, bool cfixOK,
    float2 u0prev, float u0fixprev,
    float2& u0c, float2& u1c, float2& x2c,
    float& z0, float& z1, float& zf, float& u0fc)
{
    u0c = *(const float2*)(u0in + g);
    u1c = *(const float2*)(u1in + g);
    x2c = *(const float2*)(xin  + g);
    float2 yc = *(const float2*)(yv + g);

    float u1left = __shfl_up_sync(0xffffffffu, u1c.y, 1);
    if (lane == 0) u1left = (tid > 0) ? u1in[g - 1] : 0.f;

    const bool nl = (i < HH - 1);
    float u0cx = nl ? u0c.x : 0.f;
    float u0cy = nl ? u0c.y : 0.f;
    float u1cy = (tid == NTHR - 1) ? 0.f : u1c.y;   // col 511 has no right diff

    float a0 = u0prev.x + u1left - u0cx - u1c.x;
    float a1 = u0prev.y + u1c.x  - u0cy - u1cy;

    float x0 = fmaf(TAUc, yc.x - a0, x2c.x) * INV1PTAU;
    float x1 = fmaf(TAUc, yc.y - a1, x2c.y) * INV1PTAU;
    z0 = 2.f * x0 - x2c.x;
    z1 = 2.f * x1 - x2c.y;

    zf = 0.f; u0fc = 0.f;
    if (cfixOK) {                       // lane 31 (except tid 255): column c0+2
        float u0f = u0in[g + 2];
        float u1f = u1in[g + 2];
        float x2f = xin [g + 2];
        float yf  = yv  [g + 2];
        float u0fx = nl ? u0f : 0.f;
        float af = u0fixprev + u1c.y - u0fx - u1f;
        float xf = fmaf(TAUc, yf - af, x2f) * INV1PTAU;
        zf = 2.f * xf - x2f;
        u0fc = u0f;
    }
}

__global__ void __launch_bounds__(NTHR, 4)
tv_persistent(const float* __restrict__ yv, float* __restrict__ out)
{
    const int tid  = threadIdx.x;
    const int lane = tid & 31;
    const int wid  = tid >> 5;
    const int blk  = blockIdx.x;
    const bool cfixOK = (lane == 31) && (tid != NTHR - 1);

    const int b  = blk >> 6;           // image
    const int s  = blk & 63;           // stripe within image
    const int i0 = s * ROWS;
    const int g0 = b * IMG + i0 * WW + 2 * tid;

    __shared__ float snum[NWARP], sden[NWARP];
    __shared__ float sdec;
    __shared__ int   sbase;

    if (tid == 0) sbase = g_vflag[blk];       // only we ever write our slot
    __syncthreads();
    const int base = sbase;                   // uniform across all blocks

    // ---- init own stripe: x2 = y, u = 0 ----
    {
        int gg = g0;
        const float2 zz = make_float2(0.f, 0.f);
        #pragma unroll
        for (int r = 0; r < ROWS; r++, gg += WW) {
            *(float2*)(g_x [0] + gg) = *(const float2*)(yv + gg);
            *(float2*)(g_u0[0] + gg) = zz;
            *(float2*)(g_u1[0] + gg) = zz;
        }
    }
    __threadfence();
    __syncthreads();
    if (tid == 0) g_vflag[blk] = base + 1;    // version 0 (init) published

    int  executed = NITERc;
    bool fired    = false;

    for (int t = 0; t < NITERc; t++) {
        // -- wait for neighbor stripes to reach version t (iter t-1 done) --
        if (tid == 0) {
            const int need = base + 1 + t;
            if (s > 0)       while (g_vflag[blk - 1] < need) __nanosleep(32);
            if (s < SPI - 1) while (g_vflag[blk + 1] < need) __nanosleep(32);
        }
        // -- wait for decision inputs d(t-2), then sync --
        if (t >= 4) {
            const int td = t - 2;
            for (;;) {
                bool ok = (g_ptag[td][tid] > base) &&
                          (g_ptag[td][tid + NTHR] > base);
                if (__syncthreads_and(ok)) break;
                __nanosleep(64);
            }
        } else {
            __syncthreads();
        }
        __threadfence();   // invalidate L1: fresh halos + fresh partials

        // -- evaluate decision d(t-2): identical fixed-order reduce per block --
        if (t >= 4) {
            const int td = t - 2;
            float n2 = g_pnum[td][tid] + g_pnum[td][tid + NTHR];
            float d2 = g_pden[td][tid] + g_pden[td][tid + NTHR];
            #pragma unroll
            for (int o = 16; o; o >>= 1) {
                n2 += __shfl_down_sync(0xffffffffu, n2, o);
                d2 += __shfl_down_sync(0xffffffffu, d2, o);
            }
            if (lane == 0) { snum[wid] = n2; sden[wid] = d2; }
            __syncthreads();
            if (tid == 0) {
                float N = 0.f, D = 0.f;
                #pragma unroll
                for (int w = 0; w < NWARP; w++) { N += snum[w]; D += sden[w]; }
                sdec = sqrtf(N) / sqrtf(D);
            }
            __syncthreads();
            if (sdec < CRITc) { executed = td + 1; fired = true; break; }
        }

        const int p = t & 1;
        const float* __restrict__ xin  = g_x [p];
        const float* __restrict__ u0in = g_u0[p];
        const float* __restrict__ u1in = g_u1[p];
        float* __restrict__ xout  = g_x [p ^ 1];
        float* __restrict__ u0out = g_u0[p ^ 1];
        float* __restrict__ u1out = g_u1[p ^ 1];

        // prologue: row i0
        float2 u0prev = (i0 > 0) ? *(const float2*)(u0in + g0 - WW)
                                 : make_float2(0.f, 0.f);
        float u0fixprev = (cfixOK && i0 > 0) ? u0in[g0 + 2 - WW] : 0.f;

        float2 u0c, u1c, x2c;
        float zc0, zc1, zfc, u0fc;
        row_pair(xin, u0in, u1in, yv, g0, i0, tid, lane, cfixOK,
                 u0prev, u0fixprev, u0c, u1c, x2c, zc0, zc1, zfc, u0fc);

        float num = 0.f, den = 0.f;
        int g = g0;

        #pragma unroll
        for (int r = 0; r < ROWS; r++) {
            const int i = i0 + r;

            float2 u0N = make_float2(0.f, 0.f), u1N = u0N, x2N = u0N;
            float zN0 = 0.f, zN1 = 0.f, zfN = 0.f, u0fN = 0.f;
            if (i + 1 < HH)     // block-uniform
                row_pair(xin, u0in, u1in, yv, g + WW, i + 1, tid, lane, cfixOK,
                         u0c, u0fc, u0N, u1N, x2N, zN0, zN1, zfN, u0fN);

            float dw0 = zc1 - zc0;
            float zsh = __shfl_down_sync(0xffffffffu, zc0, 1);
            float zr1 = (lane == 31) ? zfc : zsh;
            float dw1 = (tid == NTHR - 1) ? 0.f : (zr1 - zc1);

            const bool nl = (i < HH - 1);
            float dh0 = nl ? (zN0 - zc0) : 0.f;
            float dh1 = nl ? (zN1 - zc1) : 0.f;

            float v00 = fmaf(SIGMAc, dh0, u0c.x);
            float v10 = fmaf(SIGMAc, dw0, u1c.x);
            float v01 = fmaf(SIGMAc, dh1, u0c.y);
            float v11 = fmaf(SIGMAc, dw1, u1c.y);

            float m20 = fmaf(v00, v00, v10 * v10);
            float m21 = fmaf(v01, v01, v11 * v11);
            float sc0 = (m20 > THS2c) ? (THSc * rsqrtf(m20)) : 1.f;
            float sc1 = (m21 > THS2c) ? (THSc * rsqrtf(m21)) : 1.f;

            float2 xn, u0n, u1n;
            xn.x  = fmaf(HRHOc, zc0 - x2c.x, x2c.x);
            xn.y  = fmaf(HRHOc, zc1 - x2c.y, x2c.y);
            u0n.x = fmaf(RHOc, fmaf(v00, sc0, -u0c.x), u0c.x);
            u0n.y = fmaf(RHOc, fmaf(v01, sc1, -u0c.y), u0c.y);
            u1n.x = fmaf(RHOc, fmaf(v10, sc0, -u1c.x), u1c.x);
            u1n.y = fmaf(RHOc, fmaf(v11, sc1, -u1c.y), u1c.y);

            *(float2*)(xout  + g) = xn;
            *(float2*)(u0out + g) = u0n;
            *(float2*)(u1out + g) = u1n;

            float d0 = xn.x - x2c.x, d1 = xn.y - x2c.y;
            num = fmaf(d0, d0, num);  num = fmaf(d1, d1, num);
            float e0 = xn.x + 1e-12f, e1 = xn.y + 1e-12f;
            den = fmaf(e0, e0, den);  den = fmaf(e1, e1, den);

            u0c = u0N; u1c = u1N; x2c = x2N;
            zc0 = zN0; zc1 = zN1; zfc = zfN; u0fc = u0fN;
            g += WW;
        }

        // -- publish convergence partials (needed from t >= 2) --
        if (t >= 2) {
            #pragma unroll
            for (int o = 16; o; o >>= 1) {
                num += __shfl_down_sync(0xffffffffu, num, o);
                den += __shfl_down_sync(0xffffffffu, den, o);
            }
            if (lane == 0) { snum[wid] = num; sden[wid] = den; }
            __syncthreads();
            if (tid == 0) {
                float n2 = 0.f, d2 = 0.f;
                #pragma unroll
                for (int w = 0; w < NWARP; w++) { n2 += snum[w]; d2 += sden[w]; }
                g_pnum[t][blk] = n2;
                g_pden[t][blk] = d2;
            }
        }

        // -- publish this iteration's state version + partial tag --
        __threadfence();
        __syncthreads();
        if (tid == 0) {
            g_vflag[blk] = base + 2 + t;
            if (t >= 2) g_ptag[t][blk] = base + 1;
        }
    }

    // d(td) for td <= 37 checked in-loop; d(39) cannot change `executed`.
    // Still pending: d(38).
    if (!fired) {
        const int td = NITERc - 2;      // 38
        for (;;) {
            bool ok = (g_ptag[td][tid] > base) &&
                      (g_ptag[td][tid + NTHR] > base);
            if (__syncthreads_and(ok)) break;
            __nanosleep(64);
        }
        __threadfence();
        float n2 = g_pnum[td][tid] + g_pnum[td][tid + NTHR];
        float d2 = g_pden[td][tid] + g_pden[td][tid + NTHR];
        #pragma unroll
        for (int o = 16; o; o >>= 1) {
            n2 += __shfl_down_sync(0xffffffffu, n2, o);
            d2 += __shfl_down_sync(0xffffffffu, d2, o);
        }
        if (lane == 0) { snum[wid] = n2; sden[wid] = d2; }
        __syncthreads();
        if (tid == 0) {
            float N = 0.f, D = 0.f;
            #pragma unroll
            for (int w = 0; w < NWARP; w++) { N += snum[w]; D += sden[w]; }
            sdec = sqrtf(N) / sqrtf(D);
        }
        __syncthreads();
        if (sdec < CRITc) executed = td + 1;   // 39; else stays 40
    }

    // ---- write own stripe from the buffer holding the final state ----
    // (every cell was written by this very thread -> intra-thread coherence)
    const float* __restrict__ src = g_x[executed & 1];
    int gg = g0;
    #pragma unroll
    for (int r = 0; r < ROWS; r++, gg += WW)
        *(float2*)(out + gg) = *(const float2*)(src + gg);
}

extern "C" void kernel_launch(void* const* d_in, const int* in_sizes, int n_in,
                              void* d_out, int out_size) {
    const float* y = (const float*)d_in[0];
    float* out = (float*)d_out;
    tv_persistent<<<NBLK, NTHR>>>(y, out);
}

// round 6
// speedup vs baseline: 1.0861x; 1.0861x over previous
#include <cuda_runtime.h>

// Persistent-kernel TV denoiser (Chambolle-Pock, RHO-relaxed), single launch.
// 512 blocks x 256 threads; each block keeps its 8-row stripe state (x2,u0,u1)
// RESIDENT IN SHARED MEMORY for all iterations. Only stripe-boundary halos go
// through global memory (parity double-buffered). One grid barrier per iter.

#define BATCH 8
#define HH 512
#define WW 512
#define IMG (HH*WW)
#define ROWS 8
#define SPI (HH/ROWS)            // 64 stripes per image
#define NBLK (BATCH*SPI)         // 512 blocks
#define NTHR 256
#define NWARP (NTHR/32)

#define TAUc     0.01f
#define INV1PTAU (1.0f/1.01f)
#define SIGMAc   12.5f
#define RHOc     1.99f
#define HRHOc    0.995f          /* RHO/2 */
#define THSc     0.1f
#define THS2c    0.01f           /* THS^2 */
#define CRITc    1e-5f
#define NITERc   40

// Halo exchange (parity double-buffered) + convergence partials.
__device__ float g_hx2 [2][NBLK][WW];   // each block's FIRST row x2
__device__ float g_hu0f[2][NBLK][WW];   // first row u0
__device__ float g_hu1f[2][NBLK][WW];   // first row u1
__device__ float g_hu0l[2][NBLK][WW];   // LAST row u0
__device__ float g_pnum[2][NBLK];
__device__ float g_pden[2][NBLK];
__device__ unsigned int          g_count = 0;
__device__ volatile unsigned int g_gen   = 0;

__device__ __forceinline__ void grid_barrier()
{
    __threadfence();
    __syncthreads();
    if (threadIdx.x == 0) {
        unsigned int gen = g_gen;
        if (atomicInc(&g_count, NBLK - 1u) == NBLK - 1u) {
            g_gen = gen + 1u;
        } else {
            while (g_gen == gen) __nanosleep(64);
        }
    }
    __syncthreads();
    __threadfence();
}

// z = 2x - x2 for this thread's column pair in one row, plus lane-31 fixup
// column (c+2). px2/pu0/pu1 point at the row (smem stripe row or global halo
// row); py is the global y row. u0prev/u0fixprev: previous-row u0 (registers).
__device__ __forceinline__ void row_z(
    const float* __restrict__ px2, const float* __restrict__ pu0,
    const float* __restrict__ pu1, const float* __restrict__ py,
    int tid, int lane, bool cfixOK, bool nl,
    float2 u0prev, float u0fixprev,
    float2& u0c, float2& u1c, float2& x2c,
    float& z0, float& z1, float& zf, float& u0fc)
{
    const int c = 2 * tid;
    u0c = *(const float2*)(pu0 + c);
    u1c = *(const float2*)(pu1 + c);
    x2c = *(const float2*)(px2 + c);
    float2 yc = *(const float2*)(py + c);

    float u1left = __shfl_up_sync(0xffffffffu, u1c.y, 1);
    if (lane == 0) u1left = (tid > 0) ? pu1[c - 1] : 0.f;

    float u0cx = nl ? u0c.x : 0.f;
    float u0cy = nl ? u0c.y : 0.f;
    float u1cy = (tid == NTHR - 1) ? 0.f : u1c.y;   // col 511: no right diff

    float a0 = u0prev.x + u1left - u0cx - u1c.x;
    float a1 = u0prev.y + u1c.x  - u0cy - u1cy;

    float x0 = fmaf(TAUc, yc.x - a0, x2c.x) * INV1PTAU;
    float x1 = fmaf(TAUc, yc.y - a1, x2c.y) * INV1PTAU;
    z0 = 2.f * x0 - x2c.x;
    z1 = 2.f * x1 - x2c.y;

    zf = 0.f; u0fc = 0.f;
    if (cfixOK) {                       // lane 31 (not tid 255): column c+2
        float u0f = pu0[c + 2];
        float u1f = pu1[c + 2];
        float x2f = px2[c + 2];
        float yf  = py [c + 2];
        float u0fx = nl ? u0f : 0.f;
        float af = u0fixprev + u1c.y - u0fx - u1f;
        float xf = fmaf(TAUc, yf - af, x2f) * INV1PTAU;
        zf = 2.f * xf - x2f;
        u0fc = u0f;
    }
}

__global__ void __launch_bounds__(NTHR, 4)
tv_persistent(const float* __restrict__ yv, float* __restrict__ out)
{
    extern __shared__ float smem[];
    float* sx2 = smem;                  // [ROWS][WW]
    float* su0 = smem + ROWS * WW;
    float* su1 = smem + 2 * ROWS * WW;

    const int tid  = threadIdx.x;
    const int lane = tid & 31;
    const int wid  = tid >> 5;
    const int blk  = blockIdx.x;
    const bool cfixOK = (lane == 31) && (tid != NTHR - 1);

    const int b  = blk >> 6;            // image
    const int s  = blk & 63;            // stripe within image
    const int i0 = s * ROWS;
    const int c  = 2 * tid;
    const float* __restrict__ ybase = yv + b * IMG + i0 * WW;

    __shared__ float snum[NWARP], sden[NWARP];
    __shared__ float sdec;

    // ---- init stripe state in smem: x2 = y, u = 0; publish parity-0 halos ----
    {
        const float2 zz = make_float2(0.f, 0.f);
        #pragma unroll
        for (int r = 0; r < ROWS; r++) {
            float2 yr = *(const float2*)(ybase + r * WW + c);
            *(float2*)(sx2 + r * WW + c) = yr;
            *(float2*)(su0 + r * WW + c) = zz;
            *(float2*)(su1 + r * WW + c) = zz;
            if (r == 0) {
                *(float2*)(&g_hx2 [0][blk][c]) = yr;
                *(float2*)(&g_hu0f[0][blk][c]) = zz;
                *(float2*)(&g_hu1f[0][blk][c]) = zz;
            }
        }
        *(float2*)(&g_hu0l[0][blk][c]) = make_float2(0.f, 0.f);
    }
    grid_barrier();

    int executed = NITERc;

    for (int t = 0; t < NITERc; t++) {
        const int p  = t & 1;
        const int pn = p ^ 1;

        // prologue: previous-row u0 for row i0 (from above-neighbor halo)
        float2 u0prev = (s > 0) ? *(const float2*)(&g_hu0l[p][blk - 1][c])
                                : make_float2(0.f, 0.f);
        float u0fixprev = (cfixOK && s > 0) ? g_hu0l[p][blk - 1][c + 2] : 0.f;

        float2 u0c, u1c, x2c;
        float zc0, zc1, zfc, u0fc;
        row_z(sx2, su0, su1, ybase, tid, lane, cfixOK, true,
              u0prev, u0fixprev, u0c, u1c, x2c, zc0, zc1, zfc, u0fc);
        __syncthreads();   // all prologue reads of row 0 done before step 0 writes

        float num = 0.f, den = 0.f;

        #pragma unroll
        for (int r = 0; r < ROWS; r++) {
            const int i = i0 + r;
            const bool nlr = (i < HH - 1);      // block-uniform

            float2 u0N = make_float2(0.f, 0.f), u1N = u0N, x2N = u0N;
            float zN0 = 0.f, zN1 = 0.f, zfN = 0.f, u0fN = 0.f;
            if (r < ROWS - 1) {
                row_z(sx2 + (r + 1) * WW, su0 + (r + 1) * WW, su1 + (r + 1) * WW,
                      ybase + (r + 1) * WW, tid, lane, cfixOK, (i + 1 < HH - 1),
                      u0c, u0fc, u0N, u1N, x2N, zN0, zN1, zfN, u0fN);
            } else if (s < SPI - 1) {           // halo row i0+8 from below block
                row_z(g_hx2[p][blk + 1], g_hu0f[p][blk + 1], g_hu1f[p][blk + 1],
                      ybase + ROWS * WW, tid, lane, cfixOK, true,
                      u0c, u0fc, u0N, u1N, x2N, zN0, zN1, zfN, u0fN);
            }

            float dw0 = zc1 - zc0;
            float zsh = __shfl_down_sync(0xffffffffu, zc0, 1);
            float zr1 = (lane == 31) ? zfc : zsh;
            float dw1 = (tid == NTHR - 1) ? 0.f : (zr1 - zc1);

            float dh0 = nlr ? (zN0 - zc0) : 0.f;
            float dh1 = nlr ? (zN1 - zc1) : 0.f;

            float v00 = fmaf(SIGMAc, dh0, u0c.x);
            float v10 = fmaf(SIGMAc, dw0, u1c.x);
            float v01 = fmaf(SIGMAc, dh1, u0c.y);
            float v11 = fmaf(SIGMAc, dw1, u1c.y);

            float m20 = fmaf(v00, v00, v10 * v10);
            float m21 = fmaf(v01, v01, v11 * v11);
            float sc0 = (m20 > THS2c) ? (THSc * rsqrtf(m20)) : 1.f;
            float sc1 = (m21 > THS2c) ? (THSc * rsqrtf(m21)) : 1.f;

            float2 xn, u0n, u1n;
            xn.x  = fmaf(HRHOc, zc0 - x2c.x, x2c.x);
            xn.y  = fmaf(HRHOc, zc1 - x2c.y, x2c.y);
            u0n.x = fmaf(RHOc, fmaf(v00, sc0, -u0c.x), u0c.x);
            u0n.y = fmaf(RHOc, fmaf(v01, sc1, -u0c.y), u0c.y);
            u1n.x = fmaf(RHOc, fmaf(v10, sc0, -u1c.x), u1c.x);
            u1n.y = fmaf(RHOc, fmaf(v11, sc1, -u1c.y), u1c.y);

            // in-place smem update of row r (old row-r values live in regs)
            *(float2*)(sx2 + r * WW + c) = xn;
            *(float2*)(su0 + r * WW + c) = u0n;
            *(float2*)(su1 + r * WW + c) = u1n;

            if (r == 0) {                       // publish new first-row halos
                *(float2*)(&g_hx2 [pn][blk][c]) = xn;
                *(float2*)(&g_hu0f[pn][blk][c]) = u0n;
                *(float2*)(&g_hu1f[pn][blk][c]) = u1n;
            }
            if (r == ROWS - 1) {                // publish new last-row u0
                *(float2*)(&g_hu0l[pn][blk][c]) = u0n;
            }

            float d0 = xn.x - x2c.x, d1 = xn.y - x2c.y;
            num = fmaf(d0, d0, num);  num = fmaf(d1, d1, num);
            float e0 = xn.x + 1e-12f, e1 = xn.y + 1e-12f;
            den = fmaf(e0, e0, den);  den = fmaf(e1, e1, den);

            u0c = u0N; u1c = u1N; x2c = x2N;
            zc0 = zN0; zc1 = zN1; zfc = zfN; u0fc = u0fN;

            __syncthreads();   // row r fully read/written before row r+1 writes
        }

        // -- publish convergence partials (needed from t >= 2) --
        if (t >= 2) {
            #pragma unroll
            for (int o = 16; o; o >>= 1) {
                num += __shfl_down_sync(0xffffffffu, num, o);
                den += __shfl_down_sync(0xffffffffu, den, o);
            }
            if (lane == 0) { snum[wid] = num; sden[wid] = den; }
            __syncthreads();
            if (tid == 0) {
                float n2 = 0.f, d2 = 0.f;
                #pragma unroll
                for (int w = 0; w < NWARP; w++) { n2 += snum[w]; d2 += sden[w]; }
                g_pnum[p][blk] = n2;
                g_pden[p][blk] = d2;
            }
        }

        grid_barrier();

        if (t >= 2) {
            // every block redundantly reduces the 512 partials in an identical
            // fixed order -> identical float result -> identical decision.
            float n2 = g_pnum[p][tid] + g_pnum[p][tid + NTHR];
            float d2 = g_pden[p][tid] + g_pden[p][tid + NTHR];
            #pragma unroll
            for (int o = 16; o; o >>= 1) {
                n2 += __shfl_down_sync(0xffffffffu, n2, o);
                d2 += __shfl_down_sync(0xffffffffu, d2, o);
            }
            if (lane == 0) { snum[wid] = n2; sden[wid] = d2; }
            __syncthreads();
            if (tid == 0) {
                float N = 0.f, D = 0.f;
                #pragma unroll
                for (int w = 0; w < NWARP; w++) { N += snum[w]; D += sden[w]; }
                sdec = sqrtf(N) / sqrtf(D);
            }
            __syncthreads();
            if (sdec < CRITc) { executed = t + 1; break; }
            __syncthreads();   // protect snum/sden reuse next iteration
        }
    }
    (void)executed;   // smem always holds the final state x2^executed

    // ---- write own stripe from smem ----
    float* __restrict__ obase = out + b * IMG + i0 * WW;
    #pragma unroll
    for (int r = 0; r < ROWS; r++)
        *(float2*)(obase + r * WW + c) = *(const float2*)(sx2 + r * WW + c);
}

extern "C" void kernel_launch(void* const* d_in, const int* in_sizes, int n_in,
                              void* d_out, int out_size) {
    const float* y = (const float*)d_in[0];
    float* out = (float*)d_out;
    const int smem_bytes = 3 * ROWS * WW * sizeof(float);   // 48 KB dynamic
    // Opt in: dynamic smem + static smem exceeds the default 48 KB budget.
    // Host-side attribute set; not a stream op, legal during graph capture,
    // deterministic and idempotent.
    cudaFuncSetAttribute(tv_persistent,
                         cudaFuncAttributeMaxDynamicSharedMemorySize,
                         smem_bytes + 1024);
    tv_persistent<<<NBLK, NTHR, smem_bytes>>>(y, out);
}

// round 9
// speedup vs baseline: 1.4116x; 1.2997x over previous
#include <cuda_runtime.h>

// Persistent-kernel TV denoiser (Chambolle-Pock, RHO-relaxed), single launch.
// 592 blocks (= 148 SMs x 4 CTAs, perfectly balanced) x 256 threads; each
// thread owns 2 adjacent columns (float2) and marches a 6/7-row stripe carved
// from the flattened batch*H = 4096 row dimension. One grid barrier per iter.

#define WW 512
#define TOTROWS 4096             // BATCH * HH
#define NTOT (TOTROWS*WW)
#define NBLK 592                 // 148 * 4, all co-resident
#define NTHR 256
#define NWARP (NTHR/32)
#define NB7 544                  // 544*7 + 48*6 = 4096
#define R7BASE (NB7*7)           // 3808

#define TAUc     0.01f
#define INV1PTAU (1.0f/1.01f)
#define SIGMAc   12.5f
#define RHOc     1.99f
#define HRHOc    0.995f          /* RHO/2 */
#define THSc     0.1f
#define THS2c    0.01f           /* THS^2 */
#define CRITc    1e-5f
#define NITERc   40

__device__ float g_x [2][NTOT];
__device__ float g_u0[2][NTOT];
__device__ float g_u1[2][NTOT];
__device__ float g_pnum[2][NBLK];
__device__ float g_pden[2][NBLK];
__device__ unsigned int          g_count = 0;
__device__ volatile unsigned int g_gen   = 0;

__device__ __forceinline__ void grid_barrier()
{
    __threadfence();
    __syncthreads();
    if (threadIdx.x == 0) {
        unsigned int gen = g_gen;
        if (atomicInc(&g_count, NBLK - 1u) == NBLK - 1u) {
            g_gen = gen + 1u;
        } else {
            while (g_gen == gen) __nanosleep(64);
        }
    }
    __syncthreads();
    __threadfence();
}

// z = 2x - x2 for this thread's column pair in one row (element base index g),
// plus the lane-31 fixup column (c+2). nl: this row has a down-diff (image row
// != 511). u0prev/u0fixprev: previous-row u0 (0 at image top). Warp shuffles
// inside: call only with block-uniform control.
__device__ __forceinline__ void row_pair(
    const float* __restrict__ xin, const float* __restrict__ u0in,
    const float* __restrict__ u1in, const float* __restrict__ yv,
    int g, int tid, int lane, bool cfixOK, bool nl,
    float2 u0prev, float u0fixprev,
    float2& u0c, float2& u1c, float2& x2c,
    float& z0, float& z1, float& zf, float& u0fc)
{
    u0c = *(const float2*)(u0in + g);
    u1c = *(const float2*)(u1in + g);
    x2c = *(const float2*)(xin  + g);
    float2 yc = *(const float2*)(yv + g);

    float u1left = __shfl_up_sync(0xffffffffu, u1c.y, 1);
    if (lane == 0) u1left = (tid > 0) ? u1in[g - 1] : 0.f;

    float u0cx = nl ? u0c.x : 0.f;
    float u0cy = nl ? u0c.y : 0.f;
    float u1cy = (tid == NTHR - 1) ? 0.f : u1c.y;   // col 511: no right diff

    float a0 = u0prev.x + u1left - u0cx - u1c.x;
    float a1 = u0prev.y + u1c.x  - u0cy - u1cy;

    float x0 = fmaf(TAUc, yc.x - a0, x2c.x) * INV1PTAU;
    float x1 = fmaf(TAUc, yc.y - a1, x2c.y) * INV1PTAU;
    z0 = 2.f * x0 - x2c.x;
    z1 = 2.f * x1 - x2c.y;

    zf = 0.f; u0fc = 0.f;
    if (cfixOK) {                       // lane 31 (not tid 255): column c+2
        float u0f = u0in[g + 2];
        float u1f = u1in[g + 2];
        float x2f = xin [g + 2];
        float yf  = yv  [g + 2];
        float u0fx = nl ? u0f : 0.f;
        float af = u0fixprev + u1c.y - u0fx - u1f;
        float xf = fmaf(TAUc, yf - af, x2f) * INV1PTAU;
        zf = 2.f * xf - x2f;
        u0fc = u0f;
    }
}

template<int NR>
__device__ __forceinline__ void do_rows(
    const float* __restrict__ xin, const float* __restrict__ u0in,
    const float* __restrict__ u1in, const float* __restrict__ yv,
    float* __restrict__ xout, float* __restrict__ u0out,
    float* __restrict__ u1out,
    int g0, int r0, int tid, int lane, bool cfixOK,
    float& num, float& den)
{
    const float2 zz = make_float2(0.f, 0.f);

    // prologue: row r0
    const bool top0 = ((r0 & 511) == 0);
    float2 u0prev = top0 ? zz : *(const float2*)(u0in + g0 - WW);
    float u0fixprev = (cfixOK && !top0) ? u0in[g0 + 2 - WW] : 0.f;
    const bool nl0 = ((r0 & 511) != 511);

    float2 u0c, u1c, x2c;
    float zc0, zc1, zfc, u0fc;
    row_pair(xin, u0in, u1in, yv, g0, tid, lane, cfixOK, nl0,
             u0prev, u0fixprev, u0c, u1c, x2c, zc0, zc1, zfc, u0fc);

    int g = g0;
    #pragma unroll
    for (int r = 0; r < NR; r++) {
        const int  ri  = r0 + r;
        const int  img = ri & 511;
        const bool nl  = (img != 511);

        float2 u0N = zz, u1N = zz, x2N = zz;
        float zN0 = 0.f, zN1 = 0.f, zfN = 0.f, u0fN = 0.f;
        if (ri + 1 < TOTROWS) {                       // block-uniform
            const bool topN = (img == 511);           // next row = image top
            float2 up  = topN ? zz : u0c;
            float  upf = topN ? 0.f : u0fc;
            const bool nlN = (((ri + 1) & 511) != 511);
            row_pair(xin, u0in, u1in, yv, g + WW, tid, lane, cfixOK, nlN,
                     up, upf, u0N, u1N, x2N, zN0, zN1, zfN, u0fN);
        }

        float dw0 = zc1 - zc0;
        float zsh = __shfl_down_sync(0xffffffffu, zc0, 1);
        float zr1 = (lane == 31) ? zfc : zsh;
        float dw1 = (tid == NTHR - 1) ? 0.f : (zr1 - zc1);

        float dh0 = nl ? (zN0 - zc0) : 0.f;
        float dh1 = nl ? (zN1 - zc1) : 0.f;

        float v00 = fmaf(SIGMAc, dh0, u0c.x);
        float v10 = fmaf(SIGMAc, dw0, u1c.x);
        float v01 = fmaf(SIGMAc, dh1, u0c.y);
        float v11 = fmaf(SIGMAc, dw1, u1c.y);

        float m20 = fmaf(v00, v00, v10 * v10);
        float m21 = fmaf(v01, v01, v11 * v11);
        float sc0 = (m20 > THS2c) ? (THSc * rsqrtf(m20)) : 1.f;
        float sc1 = (m21 > THS2c) ? (THSc * rsqrtf(m21)) : 1.f;

        float2 xn, u0n, u1n;
        xn.x  = fmaf(HRHOc, zc0 - x2c.x, x2c.x);
        xn.y  = fmaf(HRHOc, zc1 - x2c.y, x2c.y);
        u0n.x = fmaf(RHOc, fmaf(v00, sc0, -u0c.x), u0c.x);
        u0n.y = fmaf(RHOc, fmaf(v01, sc1, -u0c.y), u0c.y);
        u1n.x = fmaf(RHOc, fmaf(v10, sc0, -u1c.x), u1c.x);
        u1n.y = fmaf(RHOc, fmaf(v11, sc1, -u1c.y), u1c.y);

        *(float2*)(xout  + g) = xn;
        *(float2*)(u0out + g) = u0n;
        *(float2*)(u1out + g) = u1n;

        float d0 = xn.x - x2c.x, d1 = xn.y - x2c.y;
        num = fmaf(d0, d0, num);  num = fmaf(d1, d1, num);
        float e0 = xn.x + 1e-12f, e1 = xn.y + 1e-12f;
        den = fmaf(e0, e0, den);  den = fmaf(e1, e1, den);

        u0c = u0N; u1c = u1N; x2c = x2N;
        zc0 = zN0; zc1 = zN1; zfc = zfN; u0fc = u0fN;
        g += WW;
    }
}

__global__ void __launch_bounds__(NTHR, 4)
tv_persistent(const float* __restrict__ yv, float* __restrict__ out)
{
    const int tid  = threadIdx.x;
    const int lane = tid & 31;
    const int wid  = tid >> 5;
    const int blk  = blockIdx.x;
    const bool cfixOK = (lane == 31) && (tid != NTHR - 1);

    const int nrows = (blk < NB7) ? 7 : 6;
    const int r0 = (blk < NB7) ? (blk * 7) : (R7BASE + (blk - NB7) * 6);
    const int g0 = r0 * WW + 2 * tid;

    __shared__ float snum[NWARP], sden[NWARP];
    __shared__ float sdec;

    // ---- init own stripe: x2 = y, u = 0 ----
    {
        int gg = g0;
        const float2 zz = make_float2(0.f, 0.f);
        for (int r = 0; r < nrows; r++, gg += WW) {
            *(float2*)(g_x [0] + gg) = *(const float2*)(yv + gg);
            *(float2*)(g_u0[0] + gg) = zz;
            *(float2*)(g_u1[0] + gg) = zz;
        }
    }
    grid_barrier();

    int executed = NITERc;

    for (int t = 0; t < NITERc; t++) {
        const int p = t & 1;
        const float* __restrict__ xin  = g_x [p];
        const float* __restrict__ u0in = g_u0[p];
        const float* __restrict__ u1in = g_u1[p];
        float* __restrict__ xout  = g_x [p ^ 1];
        float* __restrict__ u0out = g_u0[p ^ 1];
        float* __restrict__ u1out = g_u1[p ^ 1];

        float num = 0.f, den = 0.f;
        if (nrows == 7)
            do_rows<7>(xin, u0in, u1in, yv, xout, u0out, u1out,
                       g0, r0, tid, lane, cfixOK, num, den);
        else
            do_rows<6>(xin, u0in, u1in, yv, xout, u0out, u1out,
                       g0, r0, tid, lane, cfixOK, num, den);

        // -- publish convergence partials (needed from t >= 2) --
        if (t >= 2) {
            #pragma unroll
            for (int o = 16; o; o >>= 1) {
                num += __shfl_down_sync(0xffffffffu, num, o);
                den += __shfl_down_sync(0xffffffffu, den, o);
            }
            if (lane == 0) { snum[wid] = num; sden[wid] = den; }
            __syncthreads();
            if (tid == 0) {
                float n2 = 0.f, d2 = 0.f;
                #pragma unroll
                for (int w = 0; w < NWARP; w++) { n2 += snum[w]; d2 += sden[w]; }
                g_pnum[p][blk] = n2;
                g_pden[p][blk] = d2;
            }
        }

        grid_barrier();

        if (t >= 2) {
            // every block redundantly reduces the 592 partials in an identical
            // fixed order -> identical float result -> identical decision.
            float n2 = g_pnum[p][tid] + g_pnum[p][tid + NTHR];
            float d2 = g_pden[p][tid] + g_pden[p][tid + NTHR];
            if (tid < NBLK - 2 * NTHR) {          // 80 tail entries
                n2 += g_pnum[p][tid + 2 * NTHR];
                d2 += g_pden[p][tid + 2 * NTHR];
            }
            #pragma unroll
            for (int o = 16; o; o >>= 1) {
                n2 += __shfl_down_sync(0xffffffffu, n2, o);
                d2 += __shfl_down_sync(0xffffffffu, d2, o);
            }
            if (lane == 0) { snum[wid] = n2; sden[wid] = d2; }
            __syncthreads();
            if (tid == 0) {
                float N = 0.f, D = 0.f;
                #pragma unroll
                for (int w = 0; w < NWARP; w++) { N += snum[w]; D += sden[w]; }
                sdec = sqrtf(N) / sqrtf(D);
            }
            __syncthreads();
            if (sdec < CRITc) { executed = t + 1; break; }
            __syncthreads();   // protect snum/sden reuse next iteration
        }
    }

    // ---- write own stripe from the buffer holding the final state ----
    const float* __restrict__ src = g_x[executed & 1];
    int gg = g0;
    for (int r = 0; r < nrows; r++, gg += WW)
        *(float2*)(out + gg) = *(const float2*)(src + gg);
}

extern "C" void kernel_launch(void* const* d_in, const int* in_sizes, int n_in,
                              void* d_out, int out_size) {
    const float* y = (const float*)d_in[0];
    float* out = (float*)d_out;
    tv_persistent<<<NBLK, NTHR>>>(y, out);
}

// round 10
// speedup vs baseline: 1.4920x; 1.0570x over previous
#include <cuda_runtime.h>

// Persistent-kernel TV denoiser (Chambolle-Pock, RHO-relaxed), single launch.
// 592 blocks (= 148 SMs x 4 CTAs) x 128 threads; each thread owns 4 adjacent
// columns (float4) and marches a 6/7-row stripe that never crosses an image.
// One grid barrier per iteration; exact deterministic convergence decision.

#define WW 512
#define HH 512
#define IMG (HH*WW)
#define BATCH 8
#define NTOT (BATCH*IMG)
#define NTHR 128
#define NWARP (NTHR/32)
#define BPI 74                   // blocks per image
#define NBLK (BATCH*BPI)         // 592 = 148*4, all co-resident
#define NB7 68                   // stripes 0..67: 7 rows; 68..73: 6 rows

#define TAUc     0.01f
#define INV1PTAU (1.0f/1.01f)
#define SIGMAc   12.5f
#define RHOc     1.99f
#define HRHOc    0.995f          /* RHO/2 */
#define THSc     0.1f
#define THS2c    0.01f           /* THS^2 */
#define CRITc    1e-5f
#define NITERc   40

__device__ float g_x [2][NTOT];
__device__ float g_u0[2][NTOT];
__device__ float g_u1[2][NTOT];
__device__ float g_pnum[2][NBLK];
__device__ float g_pden[2][NBLK];
__device__ unsigned int          g_count = 0;
__device__ volatile unsigned int g_gen   = 0;

__device__ __forceinline__ void grid_barrier()
{
    __threadfence();
    __syncthreads();
    if (threadIdx.x == 0) {
        unsigned int gen = g_gen;
        if (atomicInc(&g_count, NBLK - 1u) == NBLK - 1u) {
            g_gen = gen + 1u;
        } else {
            while (g_gen == gen) __nanosleep(64);
        }
    }
    __syncthreads();
    __threadfence();
}

// z = 2x - x2 for this thread's 4 columns in one row, plus the lane-31 fixup
// column (c+4). nl: row has a down-diff (row != 511). u0prev/u0fixprev:
// previous-row u0 (registers / 0 at image top). Warp shuffles inside: call
// only with block-uniform control.
__device__ __forceinline__ void row_quad(
    const float* __restrict__ xin, const float* __restrict__ u0in,
    const float* __restrict__ u1in, const float* __restrict__ yv,
    int g, int tid, int lane, bool cfixOK, bool nl,
    float4 u0prev, float u0fixprev,
    float4& u0c, float4& u1c, float4& x2c,
    float4& z, float& zf, float& u0fc)
{
    u0c = *(const float4*)(u0in + g);
    u1c = *(const float4*)(u1in + g);
    x2c = *(const float4*)(xin  + g);
    float4 yc = *(const float4*)(yv + g);

    float u1left = __shfl_up_sync(0xffffffffu, u1c.w, 1);
    if (lane == 0) u1left = (tid > 0) ? u1in[g - 1] : 0.f;

    float u0x = nl ? u0c.x : 0.f;
    float u0y = nl ? u0c.y : 0.f;
    float u0z = nl ? u0c.z : 0.f;
    float u0w = nl ? u0c.w : 0.f;
    float u1w = (tid == NTHR - 1) ? 0.f : u1c.w;   // col 511: no right diff

    float ax = u0prev.x + u1left - u0x - u1c.x;
    float ay = u0prev.y + u1c.x  - u0y - u1c.y;
    float az = u0prev.z + u1c.y  - u0z - u1c.z;
    float aw = u0prev.w + u1c.z  - u0w - u1w;

    float x0 = fmaf(TAUc, yc.x - ax, x2c.x) * INV1PTAU;
    float x1 = fmaf(TAUc, yc.y - ay, x2c.y) * INV1PTAU;
    float x2 = fmaf(TAUc, yc.z - az, x2c.z) * INV1PTAU;
    float x3 = fmaf(TAUc, yc.w - aw, x2c.w) * INV1PTAU;
    z.x = 2.f * x0 - x2c.x;
    z.y = 2.f * x1 - x2c.y;
    z.z = 2.f * x2 - x2c.z;
    z.w = 2.f * x3 - x2c.w;

    zf = 0.f; u0fc = 0.f;
    if (cfixOK) {                       // lane 31 (not tid 127): column c+4
        float u0f = u0in[g + 4];
        float u1f = u1in[g + 4];
        float x2f = xin [g + 4];
        float yf  = yv  [g + 4];
        float u0fx = nl ? u0f : 0.f;
        float af = u0fixprev + u1c.w - u0fx - u1f;
        float xf = fmaf(TAUc, yf - af, x2f) * INV1PTAU;
        zf = 2.f * xf - x2f;
        u0fc = u0f;
    }
}

template<int NR>
__device__ __forceinline__ void do_rows(
    const float* __restrict__ xin, const float* __restrict__ u0in,
    const float* __restrict__ u1in, const float* __restrict__ yv,
    float* __restrict__ xout, float* __restrict__ u0out,
    float* __restrict__ u1out,
    int g0, int i0, bool isTop, bool notBottom, int tid, int lane, bool cfixOK,
    float& num, float& den)
{
    const float4 zz = make_float4(0.f, 0.f, 0.f, 0.f);

    // prologue: row i0 (i0 <= 506, so nl is always true here)
    float4 u0prev = isTop ? zz : *(const float4*)(u0in + g0 - WW);
    float u0fixprev = (cfixOK && !isTop) ? u0in[g0 + 4 - WW] : 0.f;

    float4 u0c, u1c, x2c, z;
    float zfc, u0fc;
    row_quad(xin, u0in, u1in, yv, g0, tid, lane, cfixOK, true,
             u0prev, u0fixprev, u0c, u1c, x2c, z, zfc, u0fc);

    int g = g0;
    #pragma unroll
    for (int r = 0; r < NR; r++) {
        // row i0+r has a down-diff unless it is row 511 (bottom stripe, last r)
        const bool nl = (r < NR - 1) || notBottom;

        float4 u0N = zz, u1N = zz, x2N = zz, zN = zz;
        float zfN = 0.f, u0fN = 0.f;
        if (nl) {                                    // block-uniform
            const bool nlN = (i0 + r + 1) != (HH - 1);
            row_quad(xin, u0in, u1in, yv, g + WW, tid, lane, cfixOK, nlN,
                     u0c, u0fc, u0N, u1N, x2N, zN, zfN, u0fN);
        }

        float zsh = __shfl_down_sync(0xffffffffu, z.x, 1);
        float zr  = (lane == 31) ? zfc : zsh;
        float dwx = z.y - z.x;
        float dwy = z.z - z.y;
        float dwz = z.w - z.z;
        float dww = (tid == NTHR - 1) ? 0.f : (zr - z.w);

        float dhx = nl ? (zN.x - z.x) : 0.f;
        float dhy = nl ? (zN.y - z.y) : 0.f;
        float dhz = nl ? (zN.z - z.z) : 0.f;
        float dhw = nl ? (zN.w - z.w) : 0.f;

        float v0x = fmaf(SIGMAc, dhx, u0c.x);
        float v0y = fmaf(SIGMAc, dhy, u0c.y);
        float v0z = fmaf(SIGMAc, dhz, u0c.z);
        float v0w = fmaf(SIGMAc, dhw, u0c.w);
        float v1x = fmaf(SIGMAc, dwx, u1c.x);
        float v1y = fmaf(SIGMAc, dwy, u1c.y);
        float v1z = fmaf(SIGMAc, dwz, u1c.z);
        float v1w = fmaf(SIGMAc, dww, u1c.w);

        float m2x = fmaf(v0x, v0x, v1x * v1x);
        float m2y = fmaf(v0y, v0y, v1y * v1y);
        float m2z = fmaf(v0z, v0z, v1z * v1z);
        float m2w = fmaf(v0w, v0w, v1w * v1w);
        float scx = (m2x > THS2c) ? (THSc * rsqrtf(m2x)) : 1.f;
        float scy = (m2y > THS2c) ? (THSc * rsqrtf(m2y)) : 1.f;
        float scz = (m2z > THS2c) ? (THSc * rsqrtf(m2z)) : 1.f;
        float scw = (m2w > THS2c) ? (THSc * rsqrtf(m2w)) : 1.f;

        float4 xn, u0n, u1n;
        xn.x  = fmaf(HRHOc, z.x - x2c.x, x2c.x);
        xn.y  = fmaf(HRHOc, z.y - x2c.y, x2c.y);
        xn.z  = fmaf(HRHOc, z.z - x2c.z, x2c.z);
        xn.w  = fmaf(HRHOc, z.w - x2c.w, x2c.w);
        u0n.x = fmaf(RHOc, fmaf(v0x, scx, -u0c.x), u0c.x);
        u0n.y = fmaf(RHOc, fmaf(v0y, scy, -u0c.y), u0c.y);
        u0n.z = fmaf(RHOc, fmaf(v0z, scz, -u0c.z), u0c.z);
        u0n.w = fmaf(RHOc, fmaf(v0w, scw, -u0c.w), u0c.w);
        u1n.x = fmaf(RHOc, fmaf(v1x, scx, -u1c.x), u1c.x);
        u1n.y = fmaf(RHOc, fmaf(v1y, scy, -u1c.y), u1c.y);
        u1n.z = fmaf(RHOc, fmaf(v1z, scz, -u1c.z), u1c.z);
        u1n.w = fmaf(RHOc, fmaf(v1w, scw, -u1c.w), u1c.w);

        *(float4*)(xout  + g) = xn;
        *(float4*)(u0out + g) = u0n;
        *(float4*)(u1out + g) = u1n;

        float d0 = xn.x - x2c.x, d1 = xn.y - x2c.y;
        float d2 = xn.z - x2c.z, d3 = xn.w - x2c.w;
        num = fmaf(d0, d0, num);  num = fmaf(d1, d1, num);
        num = fmaf(d2, d2, num);  num = fmaf(d3, d3, num);
        float e0 = xn.x + 1e-12f, e1 = xn.y + 1e-12f;
        float e2 = xn.z + 1e-12f, e3 = xn.w + 1e-12f;
        den = fmaf(e0, e0, den);  den = fmaf(e1, e1, den);
        den = fmaf(e2, e2, den);  den = fmaf(e3, e3, den);

        u0c = u0N; u1c = u1N; x2c = x2N;
        z = zN; zfc = zfN; u0fc = u0fN;
        g += WW;
    }
}

__global__ void __launch_bounds__(NTHR, 4)
tv_persistent(const float* __restrict__ yv, float* __restrict__ out)
{
    const int tid  = threadIdx.x;
    const int lane = tid & 31;
    const int wid  = tid >> 5;
    const int blk  = blockIdx.x;
    const bool cfixOK = (lane == 31) && (tid != NTHR - 1);

    const int b = blk / BPI;            // image
    const int s = blk - b * BPI;        // stripe within image (0..73)
    const int nrows = (s < NB7) ? 7 : 6;
    const int i0 = (s < NB7) ? (7 * s) : (7 * NB7 + 6 * (s - NB7));
    const bool isTop     = (s == 0);
    const bool notBottom = (s != BPI - 1);
    const int g0 = b * IMG + i0 * WW + 4 * tid;

    __shared__ float snum[NWARP], sden[NWARP];
    __shared__ float sdec;

    // ---- init own stripe: x2 = y, u = 0 ----
    {
        int gg = g0;
        const float4 zz = make_float4(0.f, 0.f, 0.f, 0.f);
        for (int r = 0; r < nrows; r++, gg += WW) {
            *(float4*)(g_x [0] + gg) = *(const float4*)(yv + gg);
            *(float4*)(g_u0[0] + gg) = zz;
            *(float4*)(g_u1[0] + gg) = zz;
        }
    }
    grid_barrier();

    int executed = NITERc;

    for (int t = 0; t < NITERc; t++) {
        const int p = t & 1;
        const float* __restrict__ xin  = g_x [p];
        const float* __restrict__ u0in = g_u0[p];
        const float* __restrict__ u1in = g_u1[p];
        float* __restrict__ xout  = g_x [p ^ 1];
        float* __restrict__ u0out = g_u0[p ^ 1];
        float* __restrict__ u1out = g_u1[p ^ 1];

        float num = 0.f, den = 0.f;
        if (nrows == 7)
            do_rows<7>(xin, u0in, u1in, yv, xout, u0out, u1out,
                       g0, i0, isTop, notBottom, tid, lane, cfixOK, num, den);
        else
            do_rows<6>(xin, u0in, u1in, yv, xout, u0out, u1out,
                       g0, i0, isTop, notBottom, tid, lane, cfixOK, num, den);

        // -- publish convergence partials (needed from t >= 2) --
        if (t >= 2) {
            #pragma unroll
            for (int o = 16; o; o >>= 1) {
                num += __shfl_down_sync(0xffffffffu, num, o);
                den += __shfl_down_sync(0xffffffffu, den, o);
            }
            if (lane == 0) { snum[wid] = num; sden[wid] = den; }
            __syncthreads();
            if (tid == 0) {
                float n2 = 0.f, d2 = 0.f;
                #pragma unroll
                for (int w = 0; w < NWARP; w++) { n2 += snum[w]; d2 += sden[w]; }
                g_pnum[p][blk] = n2;
                g_pden[p][blk] = d2;
            }
        }

        grid_barrier();

        if (t >= 2) {
            // every block redundantly reduces the 592 partials in an identical
            // fixed order -> identical float result -> identical decision.
            float n2 = 0.f, d2 = 0.f;
            #pragma unroll
            for (int k = 0; k < (NBLK + NTHR - 1) / NTHR; k++) {
                int idx = tid + k * NTHR;
                if (idx < NBLK) { n2 += g_pnum[p][idx]; d2 += g_pden[p][idx]; }
            }
            #pragma unroll
            for (int o = 16; o; o >>= 1) {
                n2 += __shfl_down_sync(0xffffffffu, n2, o);
                d2 += __shfl_down_sync(0xffffffffu, d2, o);
            }
            if (lane == 0) { snum[wid] = n2; sden[wid] = d2; }
            __syncthreads();
            if (tid == 0) {
                float N = 0.f, D = 0.f;
                #pragma unroll
                for (int w = 0; w < NWARP; w++) { N += snum[w]; D += sden[w]; }
                sdec = sqrtf(N) / sqrtf(D);
            }
            __syncthreads();
            if (sdec < CRITc) { executed = t + 1; break; }
            __syncthreads();   // protect snum/sden reuse next iteration
        }
    }

    // ---- write own stripe from the buffer holding the final state ----
    const float* __restrict__ src = g_x[executed & 1];
    int gg = g0;
    for (int r = 0; r < nrows; r++, gg += WW)
        *(float4*)(out + gg) = *(const float4*)(src + gg);
}

extern "C" void kernel_launch(void* const* d_in, const int* in_sizes, int n_in,
                              void* d_out, int out_size) {
    const float* y = (const float*)d_in[0];
    float* out = (float*)d_out;
    tv_persistent<<<NBLK, NTHR>>>(y, out);
}